// round 1
// baseline (speedup 1.0000x reference)
#include <cuda_runtime.h>
#include <math.h>

#define NQ    6
#define DIM   64
#define BATCH 256
#define RPB   8   // encoder rows per block

// scratch for encoder output z (B, NQ)
__device__ float g_z[BATCH * NQ];

// ---------------- complex helpers ----------------
__device__ __forceinline__ float2 cmul(float2 a, float2 b) {
    return make_float2(fmaf(a.x, b.x, -a.y * b.y), fmaf(a.x, b.y, a.y * b.x));
}
__device__ __forceinline__ float2 cadd(float2 a, float2 b) { return make_float2(a.x + b.x, a.y + b.y); }
__device__ __forceinline__ float2 cscale(float2 a, float s) { return make_float2(a.x * s, a.y * s); }
__device__ __forceinline__ float2 cconj(float2 a) { return make_float2(a.x, -a.y); }

// ---------------- encoder ----------------
__global__ void enc_kernel(const float* __restrict__ x, const float* __restrict__ W1,
                           const float* __restrict__ b1, const float* __restrict__ ln_g,
                           const float* __restrict__ ln_b, const float* __restrict__ W2,
                           const float* __restrict__ b2)
{
    __shared__ float xs[RPB * 784];
    __shared__ float hn[RPB][256];
    __shared__ float red[256];

    const int tid = threadIdx.x;
    const int row0 = blockIdx.x * RPB;

    for (int idx = tid; idx < RPB * 784; idx += 256)
        xs[idx] = x[row0 * 784 + idx];
    __syncthreads();

    float acc[RPB];
#pragma unroll
    for (int r = 0; r < RPB; r++) acc[r] = 0.f;

    const float4* w4 = reinterpret_cast<const float4*>(W1 + tid * 784);
    for (int k = 0; k < 196; k++) {
        float4 w = w4[k];
#pragma unroll
        for (int r = 0; r < RPB; r++) {
            float4 xv = reinterpret_cast<const float4*>(xs + r * 784)[k];
            acc[r] = fmaf(w.x, xv.x, acc[r]);
            acc[r] = fmaf(w.y, xv.y, acc[r]);
            acc[r] = fmaf(w.z, xv.z, acc[r]);
            acc[r] = fmaf(w.w, xv.w, acc[r]);
        }
    }

    const float bb = b1[tid], g = ln_g[tid], be = ln_b[tid];
    for (int r = 0; r < RPB; r++) {
        float h = fmaxf(acc[r] + bb, 0.f);
        red[tid] = h;
        __syncthreads();
        for (int off = 128; off > 0; off >>= 1) {
            if (tid < off) red[tid] += red[tid + off];
            __syncthreads();
        }
        float mu = red[0] * (1.f / 256.f);
        __syncthreads();
        float d = h - mu;
        red[tid] = d * d;
        __syncthreads();
        for (int off = 128; off > 0; off >>= 1) {
            if (tid < off) red[tid] += red[tid + off];
            __syncthreads();
        }
        float var = red[0] * (1.f / 256.f);
        __syncthreads();
        hn[r][tid] = d * rsqrtf(var + 1e-5f) * g + be;
    }
    __syncthreads();

    // z = tanh(hn @ W2^T + b2): warp r handles batch row r
    const int warp = tid >> 5, lane = tid & 31;
    if (warp < RPB) {
        for (int i = 0; i < NQ; i++) {
            float p = 0.f;
            for (int k = lane; k < 256; k += 32)
                p = fmaf(hn[warp][k], W2[i * 256 + k], p);
#pragma unroll
            for (int off = 16; off > 0; off >>= 1)
                p += __shfl_down_sync(0xffffffffu, p, off);
            if (lane == 0)
                g_z[(row0 + warp) * NQ + i] = tanhf(p + b2[i]);
        }
    }
}

// ---------------- circuit ----------------
__device__ __forceinline__ int ins_bit(int r, int p) {
    int low = r & ((1 << p) - 1);
    return ((r >> p) << (p + 1)) | low;
}

// U rho U^dagger on qubit-bit p, with optional depolarizing channel (lam) applied BEFORE the unitary
__device__ __forceinline__ void gate_pass(float2 (*dm)[DIM], int tid, int p,
                                          float2 U00, float2 U01, float2 U10, float2 U11,
                                          float lam)
{
    const float hl = 0.5f * (1.f + lam), ll = 0.5f * (1.f - lam);
#pragma unroll
    for (int t = 0; t < 4; t++) {
        int bl = tid + t * 256;      // 1024 2x2 blocks
        int rk = bl >> 5, rb = bl & 31;
        int i0 = ins_bit(rk, p), i1 = i0 | (1 << p);
        int j0 = ins_bit(rb, p), j1 = j0 | (1 << p);
        float2 B00 = dm[i0][j0], B01 = dm[i0][j1], B10 = dm[i1][j0], B11 = dm[i1][j1];
        if (lam != 1.f) {
            float2 na = make_float2(hl * B00.x + ll * B11.x, hl * B00.y + ll * B11.y);
            float2 nd = make_float2(hl * B11.x + ll * B00.x, hl * B11.y + ll * B00.y);
            B00 = na; B11 = nd;
            B01 = cscale(B01, lam); B10 = cscale(B10, lam);
        }
        float2 T00 = cadd(cmul(U00, B00), cmul(U01, B10));
        float2 T01 = cadd(cmul(U00, B01), cmul(U01, B11));
        float2 T10 = cadd(cmul(U10, B00), cmul(U11, B10));
        float2 T11 = cadd(cmul(U10, B01), cmul(U11, B11));
        float2 C00 = cadd(cmul(T00, cconj(U00)), cmul(T01, cconj(U01)));
        float2 C01 = cadd(cmul(T00, cconj(U10)), cmul(T01, cconj(U11)));
        float2 C10 = cadd(cmul(T10, cconj(U00)), cmul(T11, cconj(U01)));
        float2 C11 = cadd(cmul(T10, cconj(U10)), cmul(T11, cconj(U11)));
        dm[i0][j0] = C00; dm[i0][j1] = C01; dm[i1][j0] = C10; dm[i1][j1] = C11;
    }
    __syncthreads();
}

// inverse of the CNOT ring permutation with range r (CNOT(i, (i+r)%6) applied i=0..5)
__device__ __forceinline__ int pinv_ring(int x, int r) {
#pragma unroll
    for (int i = 5; i >= 0; --i) {
        int pc = 5 - i;
        int pt = 5 - ((i + r) % 6);
        if ((x >> pc) & 1) x ^= (1 << pt);
    }
    return x;
}

__device__ __forceinline__ void perm_pass(float2 (*dm)[DIM], int tid, int r) {
    float2 v[16];
    const int ki = (tid * 16) >> 6;          // constant over the 16 elements
    const int bbase = (tid * 16) & 63;
    const int sk = pinv_ring(ki, r);
#pragma unroll
    for (int e = 0; e < 16; e++)
        v[e] = dm[sk][pinv_ring(bbase + e, r)];
    __syncthreads();
#pragma unroll
    for (int e = 0; e < 16; e++)
        dm[ki][bbase + e] = v[e];
    __syncthreads();
}

__device__ __forceinline__ void make_rot(const float* __restrict__ w,
                                         float2& U00, float2& U01, float2& U10, float2& U11)
{
    float phi = w[0], th = w[1], om = w[2];
    float c, s, sa, ca, sb, cb;
    sincosf(0.5f * th, &s, &c);
    sincosf(0.5f * (phi + om), &sa, &ca);
    sincosf(0.5f * (phi - om), &sb, &cb);
    U00 = make_float2(c * ca, -c * sa);   // e^{-i(phi+om)/2} c
    U01 = make_float2(-s * cb, -s * sb);  // -e^{i(phi-om)/2} s
    U10 = make_float2(s * cb, -s * sb);   // e^{-i(phi-om)/2} s
    U11 = make_float2(c * ca, c * sa);    // e^{i(phi+om)/2} c
}

__global__ void circuit_kernel(const float* __restrict__ shared_w, const float* __restrict__ task_w,
                               const float* __restrict__ Wp, const float* __restrict__ bp,
                               float* __restrict__ out)
{
    __shared__ float2 dm[DIM][DIM];
    __shared__ float pr[DIM];
    __shared__ float evs[NQ];

    const int tid = threadIdx.x;
    const int b = blockIdx.x;

    const float P1 = 0.001f, P2 = 0.01f;
    const float lam1 = 1.f - 4.f * P1 / 3.f;
    const float lam2 = 1.f - 4.f * P2 / 3.f;
    const float lam12 = lam1 * lam2;

    // ---- initial product state: RY(pi*z_q)|0> + depolarize(p1) per qubit (real dm) ----
    {
        float aq[NQ], bq[NQ], dq[NQ];
        const float hl = 0.5f * (1.f + lam1), ll = 0.5f * (1.f - lam1);
#pragma unroll
        for (int q = 0; q < NQ; q++) {
            float th = 0.5f * 3.14159265358979323846f * g_z[b * NQ + q];
            float c, s;
            sincosf(th, &s, &c);
            float c2 = c * c, s2 = s * s, cs = c * s;
            aq[q] = hl * c2 + ll * s2;
            dq[q] = hl * s2 + ll * c2;
            bq[q] = lam1 * cs;
        }
        const int ki = (tid * 16) >> 6;
        const int bbase = (tid * 16) & 63;
#pragma unroll
        for (int e = 0; e < 16; e++) {
            int bi = bbase + e;
            float v = 1.f;
#pragma unroll
            for (int q = 0; q < NQ; q++) {
                int kb = (ki >> (5 - q)) & 1, bbit = (bi >> (5 - q)) & 1;
                v *= (kb == bbit) ? (kb ? dq[q] : aq[q]) : bq[q];
            }
            dm[ki][bi] = make_float2(v, 0.f);
        }
    }
    __syncthreads();

    // ---- shared strongly-entangling: 3 layers, rings r=1,2,3 ----
    for (int l = 0; l < 3; l++) {
        for (int i = 0; i < NQ; i++) {
            float2 U00, U01, U10, U11;
            make_rot(shared_w + (l * NQ + i) * 3, U00, U01, U10, U11);
            gate_pass(dm, tid, 5 - i, U00, U01, U10, U11, 1.f);
        }
        perm_pass(dm, tid, l + 1);
    }

    // ---- task layers (2, rings r=1,2); mid-circuit depolarizes fused into layer-0 rots ----
    for (int l = 0; l < 2; l++) {
        for (int i = 0; i < NQ; i++) {
            float2 U00, U01, U10, U11;
            make_rot(task_w + (l * NQ + i) * 3, U00, U01, U10, U11);
            float lam = (l == 0) ? ((i < 5) ? lam12 : lam1) : 1.f;
            gate_pass(dm, tid, 5 - i, U00, U01, U10, U11, lam);
        }
        perm_pass(dm, tid, l + 1);
    }

    // ---- readout: <Z_k> (final depolarize folded as lam1 scale) + projection ----
    if (tid < DIM) pr[tid] = dm[tid][tid].x;
    __syncthreads();
    if (tid < NQ) {
        float s = 0.f;
        for (int d = 0; d < DIM; ++d)
            s += ((d >> (5 - tid)) & 1) ? -pr[d] : pr[d];
        evs[tid] = s * lam1;
    }
    __syncthreads();
    if (tid < 2) {
        float o = bp[tid];
#pragma unroll
        for (int k = 0; k < NQ; k++) o = fmaf(evs[k], Wp[tid * NQ + k], o);
        out[b * 2 + tid] = o;
    }
}

extern "C" void kernel_launch(void* const* d_in, const int* in_sizes, int n_in,
                              void* d_out, int out_size)
{
    const float* x        = (const float*)d_in[0];
    const float* W1       = (const float*)d_in[1];
    const float* b1       = (const float*)d_in[2];
    const float* ln_g     = (const float*)d_in[3];
    const float* ln_b     = (const float*)d_in[4];
    const float* W2       = (const float*)d_in[5];
    const float* b2       = (const float*)d_in[6];
    const float* shared_w = (const float*)d_in[7];
    const float* task_w   = (const float*)d_in[8];
    const float* Wp       = (const float*)d_in[9];
    const float* bp       = (const float*)d_in[10];
    float* out = (float*)d_out;

    enc_kernel<<<BATCH / RPB, 256>>>(x, W1, b1, ln_g, ln_b, W2, b2);
    circuit_kernel<<<BATCH, 256>>>(shared_w, task_w, Wp, bp, out);
}

// round 2
// speedup vs baseline: 2.2700x; 2.2700x over previous
#include <cuda_runtime.h>
#include <math.h>

#define NQ    6
#define BATCH 256
#define HID   256
#define INP   784
#define LAM1  0.9986666666666667f
#define LAM2  0.9866666666666667f
#define ENC_BLOCKS 128
#define PI_F  3.14159265358979323846f

__device__ float g_h[BATCH * HID];     // relu(x@W1^T+b1)
__device__ float g_T[NQ * 4096];       // Heisenberg-evolved observables, Pauli coords

// CNOT conjugation LUT: idx = a*4+b (control,target Pauli: I=0,X=1,Y=2,Z=3)
// value = a' | b'<<2 | neg<<4  for  C (P_a⊗P_b) C = ±(P_a'⊗P_b')
__constant__ int c_lut[16] = {0,4,11,15, 5,1,14,26, 6,2,29,9, 3,7,8,12};

// ---- PTM adjoint passes (state: real 4096-vector in smem, digit q at bits [2q,2q+1]) ----

// adjoint rot: operator coeffs v' = Mz(phi)*My(theta)*Mz(omega) * v on (X,Y,Z) of qubit q
__device__ __forceinline__ void rot_adj(float* m, const float* __restrict__ w, int q, int tid)
{
    float sp, cp, st, ct, sw_, cw_;
    sincosf(w[0], &sp, &cp);
    sincosf(w[1], &st, &ct);
    sincosf(w[2], &sw_, &cw_);
    float a00 =  cp*ct*cw_ - sp*sw_, a01 =  cp*ct*sw_ + sp*cw_, a02 = -cp*st;
    float a10 = -sp*ct*cw_ - cp*sw_, a11 = -sp*ct*sw_ + cp*cw_, a12 =  sp*st;
    float a20 =  st*cw_,             a21 =  st*sw_,             a22 =  ct;
    const int d  = 1 << (2*q);
    const int lm = d - 1;
#pragma unroll
    for (int f = 0; f < 4; f++) {
        int rest = tid + f*256;
        int s0 = ((rest >> (2*q)) << (2*q + 2)) | (rest & lm);
        float vx = m[s0 + d], vy = m[s0 + 2*d], vz = m[s0 + 3*d];
        m[s0 + d]   = a00*vx + a01*vy + a02*vz;
        m[s0 + 2*d] = a10*vx + a11*vy + a12*vz;
        m[s0 + 3*d] = a20*vx + a21*vy + a22*vz;
    }
    __syncthreads();
}

// adjoint of CNOT ring with range r: conj by C5 first, then C4 ... C0; signed permutation
__device__ __forceinline__ void ring_adj(float* m, int r, int tid)
{
    float v[16]; int tg[16];
#pragma unroll
    for (int e = 0; e < 16; e++) {
        int s = tid + e*256;
        v[e] = m[s];
        int cur = s, neg = 0;
#pragma unroll
        for (int i = 5; i >= 0; --i) {
            int c = i, t = i + r; if (t >= 6) t -= 6;
            int a = (cur >> (2*c)) & 3, b = (cur >> (2*t)) & 3;
            int lv = c_lut[a*4 + b];
            cur = (cur & ~((3 << (2*c)) | (3 << (2*t))))
                | ((lv & 3) << (2*c)) | (((lv >> 2) & 3) << (2*t));
            neg ^= lv >> 4;
        }
        tg[e] = cur | (neg << 13);
    }
    __syncthreads();
#pragma unroll
    for (int e = 0; e < 16; e++)
        m[tg[e] & 4095] = (tg[e] & (1 << 13)) ? -v[e] : v[e];
    __syncthreads();
}

// all mid-circuit depolarizing channels: diagonal in Pauli basis
__device__ __forceinline__ void dep_adj(float* m, int tid)
{
#pragma unroll
    for (int e = 0; e < 16; e++) {
        int s = tid + e*256;
        float sc = 1.f;
#pragma unroll
        for (int q = 0; q < 6; q++)
            if ((s >> (2*q)) & 3) sc *= (q < 5) ? (LAM1 * LAM2) : LAM1;
        m[s] *= sc;
    }
    __syncthreads();
}

// ---- kernel 1: encoder GEMM (blocks 0..127) + Heisenberg PTM evolution (blocks 128..133) ----
__global__ void __launch_bounds__(256) k1(const float* __restrict__ x, const float* __restrict__ W1,
                                          const float* __restrict__ b1,
                                          const float* __restrict__ sw, const float* __restrict__ tw)
{
    __shared__ float sh[8 * INP];   // 25088 B; PTM branch uses first 4096 floats
    const int tid = threadIdx.x;
    const int blk = blockIdx.x;

    if (blk < ENC_BLOCKS) {
        const int rowT = blk >> 2, colT = blk & 3;
        const int row0 = rowT * 8;
        for (int r = 0; r < 8; r++)
            for (int k = tid; k < INP; k += 256)
                sh[r * INP + k] = x[(row0 + r) * INP + k];
        __syncthreads();

        const int cL = tid & 63, rg = tid >> 6;
        const int col = colT * 64 + cL;
        const float4* w4 = reinterpret_cast<const float4*>(W1 + col * INP);
        const float4* x0 = reinterpret_cast<const float4*>(sh + (rg*2) * INP);
        const float4* x1 = reinterpret_cast<const float4*>(sh + (rg*2 + 1) * INP);
        float a0 = 0.f, a1 = 0.f;
        for (int k = 0; k < INP/4; k++) {
            float4 w = w4[k], p = x0[k], q = x1[k];
            a0 = fmaf(w.x, p.x, a0); a0 = fmaf(w.y, p.y, a0);
            a0 = fmaf(w.z, p.z, a0); a0 = fmaf(w.w, p.w, a0);
            a1 = fmaf(w.x, q.x, a1); a1 = fmaf(w.y, q.y, a1);
            a1 = fmaf(w.z, q.z, a1); a1 = fmaf(w.w, q.w, a1);
        }
        const float bb = b1[col];
        g_h[(row0 + rg*2) * HID + col]     = fmaxf(a0 + bb, 0.f);
        g_h[(row0 + rg*2 + 1) * HID + col] = fmaxf(a1 + bb, 0.f);
    } else {
        float* m = sh;
        const int k = blk - ENC_BLOCKS;   // observable Z_k
        for (int i = tid; i < 4096; i += 256) m[i] = 0.f;
        __syncthreads();
        if (tid == 0) m[3 << (2*k)] = LAM1;   // final dep folded: lam1 * Z_k
        __syncthreads();

        // adjoint order: task l=1, task l=0, deps, shared l=2,1,0
        ring_adj(m, 2, tid);
        for (int i = 0; i < 6; i++) rot_adj(m, tw + (6 + i)*3, i, tid);
        ring_adj(m, 1, tid);
        for (int i = 0; i < 6; i++) rot_adj(m, tw + i*3, i, tid);
        dep_adj(m, tid);
        ring_adj(m, 3, tid);
        for (int i = 0; i < 6; i++) rot_adj(m, sw + (12 + i)*3, i, tid);
        ring_adj(m, 2, tid);
        for (int i = 0; i < 6; i++) rot_adj(m, sw + (6 + i)*3, i, tid);
        ring_adj(m, 1, tid);
        for (int i = 0; i < 6; i++) rot_adj(m, sw + i*3, i, tid);

        for (int i = tid; i < 4096; i += 256) g_T[k*4096 + i] = m[i];
    }
}

// ---- kernel 2: LayerNorm + W2/tanh + 729-term quantum eval + projection ----
__global__ void __launch_bounds__(256) k2(const float* __restrict__ lng, const float* __restrict__ lnb,
                                          const float* __restrict__ W2, const float* __restrict__ b2,
                                          const float* __restrict__ Wp, const float* __restrict__ bp,
                                          float* __restrict__ out)
{
    __shared__ float hn[HID];
    __shared__ float red[8];
    __shared__ float rx[NQ], rz[NQ], evs[NQ];
    const int tid = threadIdx.x, b = blockIdx.x;
    const int lane = tid & 31, w = tid >> 5;

    float hv = g_h[b * HID + tid];
    float s = hv;
#pragma unroll
    for (int o = 16; o > 0; o >>= 1) s += __shfl_down_sync(~0u, s, o);
    if (lane == 0) red[w] = s;
    __syncthreads();
    if (tid < 8) {
        float t = red[tid];
#pragma unroll
        for (int o = 4; o > 0; o >>= 1) t += __shfl_down_sync(0xffu, t, o);
        if (tid == 0) red[0] = t;
    }
    __syncthreads();
    float mu = red[0] * (1.f/256.f);
    __syncthreads();
    float d = hv - mu;
    s = d * d;
#pragma unroll
    for (int o = 16; o > 0; o >>= 1) s += __shfl_down_sync(~0u, s, o);
    if (lane == 0) red[w] = s;
    __syncthreads();
    if (tid < 8) {
        float t = red[tid];
#pragma unroll
        for (int o = 4; o > 0; o >>= 1) t += __shfl_down_sync(0xffu, t, o);
        if (tid == 0) red[0] = t;
    }
    __syncthreads();
    float var = red[0] * (1.f/256.f);
    hn[tid] = d * rsqrtf(var + 1e-5f) * lng[tid] + lnb[tid];
    __syncthreads();

    if (w < NQ) {
        float p = 0.f;
        for (int kk = lane; kk < 256; kk += 32)
            p = fmaf(hn[kk], W2[w*256 + kk], p);
#pragma unroll
        for (int o = 16; o > 0; o >>= 1) p += __shfl_down_sync(~0u, p, o);
        if (lane == 0) {
            float z = tanhf(p + b2[w]);
            float sn, cn;
            sincosf(PI_F * z, &sn, &cn);
            rx[w] = LAM1 * sn;   // <X> after RY + input depolarize
            rz[w] = LAM1 * cn;   // <Z>
        }
    }
    __syncthreads();

    if (w < NQ) {
        float tx[NQ], tz[NQ];
#pragma unroll
        for (int q = 0; q < NQ; q++) { tx[q] = rx[q]; tz[q] = rz[q]; }
        const float* Tw = g_T + w * 4096;
        float acc = 0.f;
        for (int s3 = lane; s3 < 729; s3 += 32) {
            int tmp = s3, s4 = 0;
            float prod = 1.f;
#pragma unroll
            for (int q = 0; q < NQ; q++) {
                int dd = tmp - (tmp/3)*3; tmp /= 3;
                if (dd == 1)      { prod *= tx[q]; s4 |= 1 << (2*q); }
                else if (dd == 2) { prod *= tz[q]; s4 |= 3 << (2*q); }
            }
            acc = fmaf(prod, Tw[s4], acc);
        }
#pragma unroll
        for (int o = 16; o > 0; o >>= 1) acc += __shfl_down_sync(~0u, acc, o);
        if (lane == 0) evs[w] = acc;
    }
    __syncthreads();

    if (tid < 2) {
        float o = bp[tid];
#pragma unroll
        for (int kq = 0; kq < NQ; kq++) o = fmaf(evs[kq], Wp[tid*NQ + kq], o);
        out[b*2 + tid] = o;
    }
}

extern "C" void kernel_launch(void* const* d_in, const int* in_sizes, int n_in,
                              void* d_out, int out_size)
{
    const float* x        = (const float*)d_in[0];
    const float* W1       = (const float*)d_in[1];
    const float* b1       = (const float*)d_in[2];
    const float* ln_g     = (const float*)d_in[3];
    const float* ln_b     = (const float*)d_in[4];
    const float* W2       = (const float*)d_in[5];
    const float* b2       = (const float*)d_in[6];
    const float* shared_w = (const float*)d_in[7];
    const float* task_w   = (const float*)d_in[8];
    const float* Wp       = (const float*)d_in[9];
    const float* bp       = (const float*)d_in[10];
    float* out = (float*)d_out;

    k1<<<ENC_BLOCKS + NQ, 256>>>(x, W1, b1, shared_w, task_w);
    k2<<<BATCH, 256>>>(ln_g, ln_b, W2, b2, Wp, bp, out);
}

// round 4
// speedup vs baseline: 2.7017x; 1.1902x over previous
#include <cuda_runtime.h>
#include <math.h>

#define NQ    6
#define BATCH 256
#define HID   256
#define INP   784
#define KS    4
#define LAM1  0.9986666666666667f
#define LAM2  0.9866666666666667f
#define PI_F  3.14159265358979323846f
#define GEMM_BLOCKS 512

__device__ float g_hp[KS * BATCH * HID];   // K-split partial GEMM outputs
__device__ float g_Tc[NQ * 729];           // compressed (base-3) evolved observables

// ---------- compile-time tables ----------
struct Tabs {
    short ring[3][4096];   // signed permutation: tg | neg<<12
    short s4of[729];       // base-3 index -> base-4 Pauli index (1->X, 2->Z)
};

static constexpr unsigned char LUTc[16] = {0,4,11,15, 5,1,14,26, 6,2,29,9, 3,7,8,12};

static constexpr Tabs make_tabs() {
    Tabs T = {};
    for (int r = 1; r <= 3; r++) {
        for (int s = 0; s < 4096; s++) {
            int cur = s, neg = 0;
            for (int i = 5; i >= 0; --i) {
                int c = i, t = (i + r) % 6;
                int a = (cur >> (2*c)) & 3, b = (cur >> (2*t)) & 3;
                int lv = LUTc[a*4 + b];
                cur = (cur & ~((3 << (2*c)) | (3 << (2*t))))
                    | ((lv & 3) << (2*c)) | (((lv >> 2) & 3) << (2*t));
                neg ^= lv >> 4;
            }
            T.ring[r-1][s] = (short)(cur | (neg << 12));
        }
    }
    for (int s = 0; s < 729; s++) {
        int tmp = s, s4 = 0;
        for (int q = 0; q < 6; q++) {
            int dd = tmp % 3; tmp /= 3;
            if (dd == 1) s4 |= 1 << (2*q);
            else if (dd == 2) s4 |= 3 << (2*q);
        }
        T.s4of[s] = (short)s4;
    }
    return T;
}
__device__ constexpr Tabs g_tabs = make_tabs();

// ---------- PTM adjoint passes (state: real 4096-vector, digit q at bits [2q,2q+1]) ----------
__device__ __forceinline__ void rot_adj(float* m, const float* __restrict__ w, int q, int tid)
{
    float sp, cp, st, ct, sw_, cw_;
    sincosf(w[0], &sp, &cp);
    sincosf(w[1], &st, &ct);
    sincosf(w[2], &sw_, &cw_);
    float a00 =  cp*ct*cw_ - sp*sw_, a01 =  cp*ct*sw_ + sp*cw_, a02 = -cp*st;
    float a10 = -sp*ct*cw_ - cp*sw_, a11 = -sp*ct*sw_ + cp*cw_, a12 =  sp*st;
    float a20 =  st*cw_,             a21 =  st*sw_,             a22 =  ct;
    const int d  = 1 << (2*q);
    const int lm = d - 1;
#pragma unroll
    for (int f = 0; f < 4; f++) {
        int rest = tid + f*256;
        int s0 = ((rest >> (2*q)) << (2*q + 2)) | (rest & lm);
        float vx = m[s0 + d], vy = m[s0 + 2*d], vz = m[s0 + 3*d];
        m[s0 + d]   = a00*vx + a01*vy + a02*vz;
        m[s0 + 2*d] = a10*vx + a11*vy + a12*vz;
        m[s0 + 3*d] = a20*vx + a21*vy + a22*vz;
    }
    __syncthreads();
}

__device__ __forceinline__ void ring_adj(float* m, int r, int tid)
{
    float v[16]; int tg[16];
    const short* tb = g_tabs.ring[r-1];
#pragma unroll
    for (int e = 0; e < 16; e++) {
        int s = tid + e*256;
        v[e] = m[s];
        tg[e] = tb[s];
    }
    __syncthreads();
#pragma unroll
    for (int e = 0; e < 16; e++)
        m[tg[e] & 4095] = (tg[e] & 4096) ? -v[e] : v[e];
    __syncthreads();
}

__device__ __forceinline__ void dep_adj(float* m, int tid)
{
#pragma unroll
    for (int e = 0; e < 16; e++) {
        int s = tid + e*256;
        float sc = 1.f;
#pragma unroll
        for (int q = 0; q < 6; q++)
            if ((s >> (2*q)) & 3) sc *= (q < 5) ? (LAM1 * LAM2) : LAM1;
        m[s] *= sc;
    }
    __syncthreads();
}

// ---------- kernel 1: K-split GEMM (blocks 0..511) + PTM evolution (512..517) ----------
__global__ void __launch_bounds__(256) k1(const float* __restrict__ x, const float* __restrict__ W1,
                                          const float* __restrict__ sw, const float* __restrict__ tw)
{
    __shared__ float sh[4096];
    const int tid = threadIdx.x;
    const int blk = blockIdx.x;

    if (blk < GEMM_BLOCKS) {
        const int rowT = blk >> 4;          // 0..31 : 8-row tiles
        const int colT = (blk >> 2) & 3;    // 0..3  : 64-col tiles
        const int kp   = blk & 3;           // 0..3  : 196-K slices

        const int row0 = rowT * 8;
        float4* sh4 = reinterpret_cast<float4*>(sh);
        const float4* x4 = reinterpret_cast<const float4*>(x);
        for (int idx = tid; idx < 8 * 49; idx += 256) {
            int r = idx / 49, c = idx % 49;
            sh4[r * 49 + c] = x4[(row0 + r) * 196 + kp * 49 + c];
        }
        __syncthreads();

        const int col = colT * 64 + (tid & 63);
        const int rg  = tid >> 6;
        const float4* w4 = reinterpret_cast<const float4*>(W1 + col * INP) + kp * 49;
        const float4* xa = reinterpret_cast<const float4*>(sh) + (rg * 2) * 49;
        const float4* xb = xa + 49;
        float a0 = 0.f, a1 = 0.f;
#pragma unroll 7
        for (int k = 0; k < 49; k++) {
            float4 w = w4[k], p = xa[k], q = xb[k];
            a0 = fmaf(w.x, p.x, a0); a0 = fmaf(w.y, p.y, a0);
            a0 = fmaf(w.z, p.z, a0); a0 = fmaf(w.w, p.w, a0);
            a1 = fmaf(w.x, q.x, a1); a1 = fmaf(w.y, q.y, a1);
            a1 = fmaf(w.z, q.z, a1); a1 = fmaf(w.w, q.w, a1);
        }
        g_hp[kp * (BATCH*HID) + (row0 + rg*2) * HID + col]     = a0;
        g_hp[kp * (BATCH*HID) + (row0 + rg*2 + 1) * HID + col] = a1;
    } else {
        float* m = sh;
        const int k = blk - GEMM_BLOCKS;    // observable Z_k
        for (int i = tid; i < 4096; i += 256) m[i] = 0.f;
        __syncthreads();
        if (tid == 0) m[3 << (2*k)] = LAM1;   // final depolarize folded
        __syncthreads();

        // adjoint order: task l=1, task l=0, mid deps, shared l=2,1,0
        ring_adj(m, 2, tid);
        for (int i = 0; i < 6; i++) rot_adj(m, tw + (6 + i)*3, i, tid);
        ring_adj(m, 1, tid);
        for (int i = 0; i < 6; i++) rot_adj(m, tw + i*3, i, tid);
        dep_adj(m, tid);
        ring_adj(m, 3, tid);
        for (int i = 0; i < 6; i++) rot_adj(m, sw + (12 + i)*3, i, tid);
        ring_adj(m, 2, tid);
        for (int i = 0; i < 6; i++) rot_adj(m, sw + (6 + i)*3, i, tid);
        ring_adj(m, 1, tid);
        for (int i = 0; i < 6; i++) rot_adj(m, sw + i*3, i, tid);

        // compress to base-3 (Y components drop: initial Bloch vectors have y=0)
        for (int i = tid; i < 729; i += 256)
            g_Tc[k * 729 + i] = m[g_tabs.s4of[i]];
    }
}

// ---------- kernel 2: bias/ReLU + LayerNorm + W2/tanh + quantum eval + projection ----------
__global__ void __launch_bounds__(256) k2(const float* __restrict__ b1,
                                          const float* __restrict__ lng, const float* __restrict__ lnb,
                                          const float* __restrict__ W2, const float* __restrict__ b2,
                                          const float* __restrict__ Wp, const float* __restrict__ bp,
                                          float* __restrict__ out)
{
    __shared__ float hn[HID];
    __shared__ float red[8];
    __shared__ float tq[18];           // [q][d]: {1, tx_q, tz_q}
    __shared__ float plo[27], phi27[27];
    __shared__ float r6[8][6];
    __shared__ float evs[NQ];

    const int tid = threadIdx.x, b = blockIdx.x;
    const int lane = tid & 31, w = tid >> 5;

    float h = g_hp[0*(BATCH*HID) + b*HID + tid] + g_hp[1*(BATCH*HID) + b*HID + tid]
            + g_hp[2*(BATCH*HID) + b*HID + tid] + g_hp[3*(BATCH*HID) + b*HID + tid]
            + b1[tid];
    h = fmaxf(h, 0.f);

    float s = h;
#pragma unroll
    for (int o = 16; o > 0; o >>= 1) s += __shfl_down_sync(~0u, s, o);
    if (lane == 0) red[w] = s;
    __syncthreads();
    if (tid < 8) {
        float t = red[tid];
#pragma unroll
        for (int o = 4; o > 0; o >>= 1) t += __shfl_down_sync(0xffu, t, o);
        if (tid == 0) red[0] = t;
    }
    __syncthreads();
    float mu = red[0] * (1.f/256.f);
    __syncthreads();
    float d = h - mu;
    s = d * d;
#pragma unroll
    for (int o = 16; o > 0; o >>= 1) s += __shfl_down_sync(~0u, s, o);
    if (lane == 0) red[w] = s;
    __syncthreads();
    if (tid < 8) {
        float t = red[tid];
#pragma unroll
        for (int o = 4; o > 0; o >>= 1) t += __shfl_down_sync(0xffu, t, o);
        if (tid == 0) red[0] = t;
    }
    __syncthreads();
    float var = red[0] * (1.f/256.f);
    hn[tid] = d * rsqrtf(var + 1e-5f) * lng[tid] + lnb[tid];
    __syncthreads();

    // z_i = tanh(hn @ W2^T + b2); Bloch components tx = lam1*sin(pi z), tz = lam1*cos(pi z)
    if (w < NQ) {
        float p = 0.f;
#pragma unroll
        for (int it = 0; it < 8; it++) {
            int kk = lane + it * 32;
            p = fmaf(hn[kk], W2[w*256 + kk], p);
        }
#pragma unroll
        for (int o = 16; o > 0; o >>= 1) p += __shfl_down_sync(~0u, p, o);
        if (lane == 0) {
            float z = tanhf(p + b2[w]);
            float sn, cn;
            sincosf(PI_F * z, &sn, &cn);
            tq[w*3 + 0] = 1.f;
            tq[w*3 + 1] = LAM1 * sn;
            tq[w*3 + 2] = LAM1 * cn;
        }
    }
    __syncthreads();

    // half-products over qubits {0,1,2} and {3,4,5}
    if (tid < 27) {
        int d0 = tid % 3, d1 = (tid / 3) % 3, d2 = tid / 9;
        plo[tid]   = tq[0*3 + d0] * tq[1*3 + d1] * tq[2*3 + d2];
        phi27[tid] = tq[3*3 + d0] * tq[4*3 + d1] * tq[5*3 + d2];
    }
    __syncthreads();

    // eval: ev_k = sum_s Tc[k][s] * plo[s%27] * phi[s/27]
    float acc[NQ] = {0.f, 0.f, 0.f, 0.f, 0.f, 0.f};
#pragma unroll
    for (int j = 0; j < 3; j++) {
        int ss = tid + j * 256;
        if (ss < 729) {
            float pr = plo[ss % 27] * phi27[ss / 27];
#pragma unroll
            for (int k = 0; k < NQ; k++)
                acc[k] = fmaf(pr, __ldg(&g_Tc[k*729 + ss]), acc[k]);
        }
    }
#pragma unroll
    for (int k = 0; k < NQ; k++) {
        float a = acc[k];
#pragma unroll
        for (int o = 16; o > 0; o >>= 1) a += __shfl_down_sync(~0u, a, o);
        if (lane == 0) r6[w][k] = a;
    }
    __syncthreads();
    if (tid < NQ) {
        float t = 0.f;
#pragma unroll
        for (int ww = 0; ww < 8; ww++) t += r6[ww][tid];
        evs[tid] = t;
    }
    __syncthreads();
    if (tid < 2) {
        float o = bp[tid];
#pragma unroll
        for (int kq = 0; kq < NQ; kq++) o = fmaf(evs[kq], Wp[tid*NQ + kq], o);
        out[b*2 + tid] = o;
    }
}

extern "C" void kernel_launch(void* const* d_in, const int* in_sizes, int n_in,
                              void* d_out, int out_size)
{
    const float* x        = (const float*)d_in[0];
    const float* W1       = (const float*)d_in[1];
    const float* b1       = (const float*)d_in[2];
    const float* ln_g     = (const float*)d_in[3];
    const float* ln_b     = (const float*)d_in[4];
    const float* W2       = (const float*)d_in[5];
    const float* b2       = (const float*)d_in[6];
    const float* shared_w = (const float*)d_in[7];
    const float* task_w   = (const float*)d_in[8];
    const float* Wp       = (const float*)d_in[9];
    const float* bp       = (const float*)d_in[10];
    float* out = (float*)d_out;

    k1<<<GEMM_BLOCKS + NQ, 256>>>(x, W1, shared_w, task_w);
    k2<<<BATCH, 256>>>(b1, ln_g, ln_b, W2, b2, Wp, bp, out);
}

// round 6
// speedup vs baseline: 3.1911x; 1.1812x over previous
#include <cuda_runtime.h>
#include <math.h>

#define NQ    6
#define BATCH 256
#define HID   256
#define INP   784
#define KS    4
#define LAM1  0.9986666666666667f
#define LAM2  0.9866666666666667f
#define LAM12 (LAM1*LAM2)
#define PI_F  3.14159265358979323846f
#define NPTM  6
#define GEMM_BLOCKS 512

__device__ float g_hp[KS * BATCH * HID];   // K-split partial GEMM outputs
__device__ float g_Tc[NQ * 729];           // compressed (base-3) evolved observables

// ---------- compile-time tables ----------
struct alignas(16) Tabs {
    short ring[3][4096];   // signed permutation: tg | neg<<12
    short s4of[736];       // base-3 index -> base-4 Pauli index (1->X, 2->Z), padded
};

static constexpr unsigned char LUTc[16] = {0,4,11,15, 5,1,14,26, 6,2,29,9, 3,7,8,12};

static constexpr Tabs make_tabs() {
    Tabs T = {};
    for (int r = 1; r <= 3; r++) {
        for (int s = 0; s < 4096; s++) {
            int cur = s, neg = 0;
            for (int i = 5; i >= 0; --i) {
                int c = i, t = (i + r) % 6;
                int a = (cur >> (2*c)) & 3, b = (cur >> (2*t)) & 3;
                int lv = LUTc[a*4 + b];
                cur = (cur & ~((3 << (2*c)) | (3 << (2*t))))
                    | ((lv & 3) << (2*c)) | (((lv >> 2) & 3) << (2*t));
                neg ^= lv >> 4;
            }
            T.ring[r-1][s] = (short)(cur | (neg << 12));
        }
    }
    for (int s = 0; s < 729; s++) {
        int tmp = s, s4 = 0;
        for (int q = 0; q < 6; q++) {
            int dd = tmp % 3; tmp /= 3;
            if (dd == 1) s4 |= 1 << (2*q);
            else if (dd == 2) s4 |= 3 << (2*q);
        }
        T.s4of[s] = (short)s4;
    }
    return T;
}
__device__ constexpr Tabs g_tabs = make_tabs();

// ---------- PTM passes over smem (state: real 4096-vector, digit q at bits [2q,2q+1]) ----------
__device__ __forceinline__ void rot_pass(float* m, const float* a, int q, int tid)
{
    float a00=a[0], a01=a[1], a02=a[2], a10=a[3], a11=a[4], a12=a[5], a20=a[6], a21=a[7], a22=a[8];
    const int d  = 1 << (2*q);
    const int lm = d - 1;
#pragma unroll
    for (int f = 0; f < 4; f++) {
        int rest = tid + f*256;
        int s0 = ((rest >> (2*q)) << (2*q + 2)) | (rest & lm);
        float vx = m[s0 + d], vy = m[s0 + 2*d], vz = m[s0 + 3*d];
        m[s0 + d]   = a00*vx + a01*vy + a02*vz;
        m[s0 + 2*d] = a10*vx + a11*vy + a12*vz;
        m[s0 + 3*d] = a20*vx + a21*vy + a22*vz;
    }
    __syncthreads();
}

__device__ __forceinline__ void ring_pass(float* m, const short* tb, int tid, bool dep)
{
    float v[16]; int tg[16];
#pragma unroll
    for (int e = 0; e < 16; e++) {
        int s = tid + e*256;
        float x = m[s];
        if (dep) {
            float sc = 1.f;
#pragma unroll
            for (int q = 0; q < 6; q++)
                if ((s >> (2*q)) & 3) sc *= (q < 5) ? LAM12 : LAM1;
            x *= sc;
        }
        v[e] = x;
        tg[e] = tb[s];
    }
    __syncthreads();
#pragma unroll
    for (int e = 0; e < 16; e++)
        m[tg[e] & 4095] = (tg[e] & 4096) ? -v[e] : v[e];
    __syncthreads();
}

// ---------- kernel 1: PTM evolution (blocks 0..5) + K-split GEMM (blocks 6..517) ----------
__global__ void __launch_bounds__(256) k1(const float* __restrict__ x, const float* __restrict__ W1,
                                          const float* __restrict__ sw, const float* __restrict__ tw)
{
    __shared__ float sh[6272];            // GEMM staging (25088B); PTM state uses first 4096 floats
    __shared__ short rtab[3][4096];       // PTM only: ring tables (24KB)
    __shared__ float mats[30][10];        // PTM only: precomputed 3x3 rot matrices

    const int tid = threadIdx.x;
    const int blk = blockIdx.x;

    if (blk < NPTM) {
        const int k = blk;    // observable Z_k
        // bulk-copy ring tables to smem (issued first; latency hidden)
        {
            const uint4* src = reinterpret_cast<const uint4*>(&g_tabs.ring[0][0]);
            uint4* dst = reinterpret_cast<uint4*>(&rtab[0][0]);
#pragma unroll
            for (int i = 0; i < 6; i++) dst[tid + i*256] = src[tid + i*256];
        }
        // precompute all 30 rotation matrices in parallel (adjoint coefficients)
        if (tid < 30) {
            const float* wsrc = (tid < 18) ? (sw + tid*3) : (tw + (tid - 18)*3);
            float sp, cp, st, ct, sw_, cw_;
            sincosf(wsrc[0], &sp, &cp);
            sincosf(wsrc[1], &st, &ct);
            sincosf(wsrc[2], &sw_, &cw_);
            mats[tid][0] =  cp*ct*cw_ - sp*sw_;
            mats[tid][1] =  cp*ct*sw_ + sp*cw_;
            mats[tid][2] = -cp*st;
            mats[tid][3] = -sp*ct*cw_ - cp*sw_;
            mats[tid][4] = -sp*ct*sw_ + cp*cw_;
            mats[tid][5] =  sp*st;
            mats[tid][6] =  st*cw_;
            mats[tid][7] =  st*sw_;
            mats[tid][8] =  ct;
        }
        float* m = sh;
        const int z0 = 3 << (2*k);
#pragma unroll
        for (int e = 0; e < 16; e++) {
            int s = tid + e*256;
            m[s] = (s == z0) ? LAM1 : 0.f;     // final depolarize folded
        }
        __syncthreads();

        // adjoint order: task l=1, task l=0, mid deps (folded into ring3), shared l=2,1,0
        ring_pass(m, rtab[1], tid, false);                         // r=2
        for (int i = 0; i < 6; i++) rot_pass(m, mats[24 + i], i, tid);
        ring_pass(m, rtab[0], tid, false);                         // r=1
        for (int i = 0; i < 6; i++) rot_pass(m, mats[18 + i], i, tid);
        ring_pass(m, rtab[2], tid, true);                          // r=3 (+dep)
        for (int i = 0; i < 6; i++) rot_pass(m, mats[12 + i], i, tid);
        ring_pass(m, rtab[1], tid, false);                         // r=2
        for (int i = 0; i < 6; i++) rot_pass(m, mats[6 + i], i, tid);
        ring_pass(m, rtab[0], tid, false);                         // r=1
        for (int i = 0; i < 6; i++) rot_pass(m, mats[i], i, tid);

        // compress to base-3 (Y components drop: initial Bloch vectors have y=0)
        for (int i = tid; i < 729; i += 256)
            g_Tc[k * 729 + i] = m[g_tabs.s4of[i]];
    } else {
        const int g    = blk - NPTM;
        const int rowT = g >> 4;            // 0..31 : 8-row tiles
        const int colT = (g >> 2) & 3;      // 0..3  : 64-col tiles
        const int kp   = g & 3;             // 0..3  : 196-K slices

        const int row0 = rowT * 8;
        float4* sh4 = reinterpret_cast<float4*>(sh);
        const float4* x4 = reinterpret_cast<const float4*>(x);
        for (int idx = tid; idx < 8 * 49; idx += 256) {
            int r = idx / 49, c = idx % 49;
            sh4[r * 49 + c] = x4[(row0 + r) * 196 + kp * 49 + c];
        }
        __syncthreads();

        const int col = colT * 64 + (tid & 63);
        const int rg  = tid >> 6;
        const float4* w4 = reinterpret_cast<const float4*>(W1 + col * INP) + kp * 49;
        const float4* xa = reinterpret_cast<const float4*>(sh) + (rg * 2) * 49;
        const float4* xb = xa + 49;
        float a0 = 0.f, a1 = 0.f;
#pragma unroll 7
        for (int k = 0; k < 49; k++) {
            float4 w = w4[k], p = xa[k], q = xb[k];
            a0 = fmaf(w.x, p.x, a0); a0 = fmaf(w.y, p.y, a0);
            a0 = fmaf(w.z, p.z, a0); a0 = fmaf(w.w, p.w, a0);
            a1 = fmaf(w.x, q.x, a1); a1 = fmaf(w.y, q.y, a1);
            a1 = fmaf(w.z, q.z, a1); a1 = fmaf(w.w, q.w, a1);
        }
        g_hp[kp * (BATCH*HID) + (row0 + rg*2) * HID + col]     = a0;
        g_hp[kp * (BATCH*HID) + (row0 + rg*2 + 1) * HID + col] = a1;
    }
}

// ---------- kernel 2: 2 batch rows per block; bias/ReLU + LN + W2/tanh + eval + projection ----------
__global__ void __launch_bounds__(256) k2(const float* __restrict__ b1v,
                                          const float* __restrict__ lng, const float* __restrict__ lnb,
                                          const float* __restrict__ W2, const float* __restrict__ b2,
                                          const float* __restrict__ Wp, const float* __restrict__ bp,
                                          float* __restrict__ out)
{
    __shared__ float hnA[HID], hnB[HID];
    __shared__ float4 red[8];
    __shared__ float tqA[18], tqB[18];
    __shared__ float ploA[27], phiA[27], ploB[27], phiB[27];
    __shared__ float r6A[8][6], r6B[8][6];
    __shared__ float evA[NQ], evB[NQ];

    const int tid = threadIdx.x;
    const int lane = tid & 31, w = tid >> 5;
    const int rA = blockIdx.x * 2, rB = rA + 1;

    // prefetch observable tables into registers (independent of everything below)
    float tcr[3][6];
#pragma unroll
    for (int j = 0; j < 3; j++) {
        int ss = tid + j * 256;
        bool ok = ss < 729;
        int sc = ok ? ss : 728;
#pragma unroll
        for (int k = 0; k < 6; k++) tcr[j][k] = ok ? g_Tc[k*729 + sc] : 0.f;
    }
    // prefetch W2 row for this warp's observable
    float w2r[8];
    if (w < NQ) {
#pragma unroll
        for (int it = 0; it < 8; it++) w2r[it] = W2[w*256 + lane + it*32];
    }

    float hA = g_hp[rA*HID + tid] + g_hp[1*(BATCH*HID) + rA*HID + tid]
             + g_hp[2*(BATCH*HID) + rA*HID + tid] + g_hp[3*(BATCH*HID) + rA*HID + tid] + b1v[tid];
    float hB = g_hp[rB*HID + tid] + g_hp[1*(BATCH*HID) + rB*HID + tid]
             + g_hp[2*(BATCH*HID) + rB*HID + tid] + g_hp[3*(BATCH*HID) + rB*HID + tid] + b1v[tid];
    hA = fmaxf(hA, 0.f);
    hB = fmaxf(hB, 0.f);

    // fused sum + sumsq reduction, both rows
    float s0 = hA, q0 = hA*hA, s1 = hB, q1 = hB*hB;
#pragma unroll
    for (int o = 16; o > 0; o >>= 1) {
        s0 += __shfl_down_sync(~0u, s0, o);
        q0 += __shfl_down_sync(~0u, q0, o);
        s1 += __shfl_down_sync(~0u, s1, o);
        q1 += __shfl_down_sync(~0u, q1, o);
    }
    if (lane == 0) red[w] = make_float4(s0, q0, s1, q1);
    __syncthreads();
    if (tid < 8) {
        float4 t = red[tid];
#pragma unroll
        for (int o = 4; o > 0; o >>= 1) {
            t.x += __shfl_down_sync(0xffu, t.x, o);
            t.y += __shfl_down_sync(0xffu, t.y, o);
            t.z += __shfl_down_sync(0xffu, t.z, o);
            t.w += __shfl_down_sync(0xffu, t.w, o);
        }
        if (tid == 0) red[0] = t;
    }
    __syncthreads();
    float4 R = red[0];
    float muA = R.x * (1.f/256.f), vaA = R.y * (1.f/256.f) - muA*muA;
    float muB = R.z * (1.f/256.f), vaB = R.w * (1.f/256.f) - muB*muB;
    float gg = lng[tid], bb = lnb[tid];
    hnA[tid] = (hA - muA) * rsqrtf(vaA + 1e-5f) * gg + bb;
    hnB[tid] = (hB - muB) * rsqrtf(vaB + 1e-5f) * gg + bb;
    __syncthreads();

    // z = tanh(hn @ W2^T + b2); Bloch: tx = lam1*sin(pi z), tz = lam1*cos(pi z)
    if (w < NQ) {
        float pA = 0.f, pB = 0.f;
#pragma unroll
        for (int it = 0; it < 8; it++) {
            int kk = lane + it * 32;
            pA = fmaf(hnA[kk], w2r[it], pA);
            pB = fmaf(hnB[kk], w2r[it], pB);
        }
#pragma unroll
        for (int o = 16; o > 0; o >>= 1) {
            pA += __shfl_down_sync(~0u, pA, o);
            pB += __shfl_down_sync(~0u, pB, o);
        }
        if (lane == 0) {
            float bw = b2[w];
            float zA = tanhf(pA + bw), zB = tanhf(pB + bw);
            float snA, cnA, snB, cnB;
            sincosf(PI_F * zA, &snA, &cnA);
            sincosf(PI_F * zB, &snB, &cnB);
            tqA[w*3] = 1.f; tqA[w*3+1] = LAM1 * snA; tqA[w*3+2] = LAM1 * cnA;
            tqB[w*3] = 1.f; tqB[w*3+1] = LAM1 * snB; tqB[w*3+2] = LAM1 * cnB;
        }
    }
    __syncthreads();

    // half-products over qubits {0,1,2} and {3,4,5}
    if (tid < 27) {
        int d0 = tid % 3, d1 = (tid / 3) % 3, d2 = tid / 9;
        ploA[tid] = tqA[d0]     * tqA[3 + d1]  * tqA[6 + d2];
        phiA[tid] = tqA[9 + d0] * tqA[12 + d1] * tqA[15 + d2];
        ploB[tid] = tqB[d0]     * tqB[3 + d1]  * tqB[6 + d2];
        phiB[tid] = tqB[9 + d0] * tqB[12 + d1] * tqB[15 + d2];
    }
    __syncthreads();

    // eval both rows against registered tables
    float accA[NQ] = {0,0,0,0,0,0}, accB[NQ] = {0,0,0,0,0,0};
#pragma unroll
    for (int j = 0; j < 3; j++) {
        int ss = tid + j * 256;
        int sc = (ss < 729) ? ss : 728;         // tcr is 0 there, so value irrelevant
        int lo = sc % 27, hi = sc / 27;
        float prA = ploA[lo] * phiA[hi];
        float prB = ploB[lo] * phiB[hi];
#pragma unroll
        for (int k = 0; k < 6; k++) {
            accA[k] = fmaf(prA, tcr[j][k], accA[k]);
            accB[k] = fmaf(prB, tcr[j][k], accB[k]);
        }
    }
#pragma unroll
    for (int k = 0; k < 6; k++) {
        float a = accA[k], b = accB[k];
#pragma unroll
        for (int o = 16; o > 0; o >>= 1) {
            a += __shfl_down_sync(~0u, a, o);
            b += __shfl_down_sync(~0u, b, o);
        }
        if (lane == 0) { r6A[w][k] = a; r6B[w][k] = b; }
    }
    __syncthreads();
    if (tid < NQ) {
        float t = 0.f;
#pragma unroll
        for (int ww = 0; ww < 8; ww++) t += r6A[ww][tid];
        evA[tid] = t;
    } else if (tid >= 32 && tid < 32 + NQ) {
        int k = tid - 32;
        float t = 0.f;
#pragma unroll
        for (int ww = 0; ww < 8; ww++) t += r6B[ww][k];
        evB[k] = t;
    }
    __syncthreads();
    if (tid < 2) {
        float o = bp[tid];
#pragma unroll
        for (int kq = 0; kq < NQ; kq++) o = fmaf(evA[kq], Wp[tid*NQ + kq], o);
        out[rA*2 + tid] = o;
    } else if (tid >= 32 && tid < 34) {
        int t2 = tid - 32;
        float o = bp[t2];
#pragma unroll
        for (int kq = 0; kq < NQ; kq++) o = fmaf(evB[kq], Wp[t2*NQ + kq], o);
        out[rB*2 + t2] = o;
    }
}

extern "C" void kernel_launch(void* const* d_in, const int* in_sizes, int n_in,
                              void* d_out, int out_size)
{
    const float* x        = (const float*)d_in[0];
    const float* W1       = (const float*)d_in[1];
    const float* b1       = (const float*)d_in[2];
    const float* ln_g     = (const float*)d_in[3];
    const float* ln_b     = (const float*)d_in[4];
    const float* W2       = (const float*)d_in[5];
    const float* b2       = (const float*)d_in[6];
    const float* shared_w = (const float*)d_in[7];
    const float* task_w   = (const float*)d_in[8];
    const float* Wp       = (const float*)d_in[9];
    const float* bp       = (const float*)d_in[10];
    float* out = (float*)d_out;

    k1<<<NPTM + GEMM_BLOCKS, 256>>>(x, W1, shared_w, task_w);
    k2<<<BATCH / 2, 256>>>(b1, ln_g, ln_b, W2, b2, Wp, bp, out);
}

// round 7
// speedup vs baseline: 5.3704x; 1.6829x over previous
#include <cuda_runtime.h>
#include <math.h>

#define NQ    6
#define BATCH 256
#define HID   256
#define INP   784
#define KS    4
#define LAM1  0.9986666666666667f
#define LAM2  0.9866666666666667f
#define LAM12 (LAM1*LAM2)
#define PI_F  3.14159265358979323846f
#define NPTM  6
#define GEMM_BLOCKS 128

__device__ float g_hp[KS * BATCH * HID];   // K-split partial GEMM outputs
__device__ float g_Tct[768 * 8];           // evolved observables, [term][obs] padded

// ---------- compile-time tables ----------
struct alignas(16) Tabs {
    short ring[3][4096];   // signed permutation: tg | neg<<12
    short s4of[736];       // base-3 index -> base-4 Pauli index (1->X, 2->Z), padded
};

static constexpr unsigned char LUTc[16] = {0,4,11,15, 5,1,14,26, 6,2,29,9, 3,7,8,12};

static constexpr Tabs make_tabs() {
    Tabs T = {};
    for (int r = 1; r <= 3; r++) {
        for (int s = 0; s < 4096; s++) {
            int cur = s, neg = 0;
            for (int i = 5; i >= 0; --i) {
                int c = i, t = (i + r) % 6;
                int a = (cur >> (2*c)) & 3, b = (cur >> (2*t)) & 3;
                int lv = LUTc[a*4 + b];
                cur = (cur & ~((3 << (2*c)) | (3 << (2*t))))
                    | ((lv & 3) << (2*c)) | (((lv >> 2) & 3) << (2*t));
                neg ^= lv >> 4;
            }
            T.ring[r-1][s] = (short)(cur | (neg << 12));
        }
    }
    for (int s = 0; s < 729; s++) {
        int tmp = s, s4 = 0;
        for (int q = 0; q < 6; q++) {
            int dd = tmp % 3; tmp /= 3;
            if (dd == 1) s4 |= 1 << (2*q);
            else if (dd == 2) s4 |= 3 << (2*q);
        }
        T.s4of[s] = (short)s4;
    }
    return T;
}
__device__ constexpr Tabs g_tabs = make_tabs();

// smem layout (union): PTM: m[4096]f @0 | rtab @16384 (24KB) | mats @40960 (1.2KB)
//                      GEMM: ws[64][101]f @0 (25856B) | xs[32][100]f @25856 (12800B)
#define SMEM_BYTES 43008

// physical index: XOR-swizzle so 64B chunks are bank-spread
__device__ __forceinline__ int SW(int s) { return s ^ (((s >> 4) & 7) << 2); }

// ---------- PTM passes ----------
// fused rotation on qubits 0 and 1 (digits at bits 0-1, 2-3); thread owns 16 contiguous
// logical elements, accessed as 4 swizzled float4s (conflict-free LDS/STS.128)
__device__ __forceinline__ void rot01_pass(float* m, const float* A0, const float* A1, int tid)
{
    float4* m4 = reinterpret_cast<float4*>(m);
    const int p = tid & 7;
    float4 v[4];
#pragma unroll
    for (int i = 0; i < 4; i++) v[i] = m4[(4*tid + i) ^ p];
    // R0 acts on digit0 (components y,z,w within each float4)
#pragma unroll
    for (int i = 0; i < 4; i++) {
        float x = v[i].y, y = v[i].z, z = v[i].w;
        v[i].y = A0[0]*x + A0[1]*y + A0[2]*z;
        v[i].z = A0[3]*x + A0[4]*y + A0[5]*z;
        v[i].w = A0[6]*x + A0[7]*y + A0[8]*z;
    }
    // R1 acts on digit1 (across float4s 1..3, per component)
    {
        float4 a = v[1], b = v[2], c = v[3];
        v[1].x = A1[0]*a.x + A1[1]*b.x + A1[2]*c.x;
        v[1].y = A1[0]*a.y + A1[1]*b.y + A1[2]*c.y;
        v[1].z = A1[0]*a.z + A1[1]*b.z + A1[2]*c.z;
        v[1].w = A1[0]*a.w + A1[1]*b.w + A1[2]*c.w;
        v[2].x = A1[3]*a.x + A1[4]*b.x + A1[5]*c.x;
        v[2].y = A1[3]*a.y + A1[4]*b.y + A1[5]*c.y;
        v[2].z = A1[3]*a.z + A1[4]*b.z + A1[5]*c.z;
        v[2].w = A1[3]*a.w + A1[4]*b.w + A1[5]*c.w;
        v[3].x = A1[6]*a.x + A1[7]*b.x + A1[8]*c.x;
        v[3].y = A1[6]*a.y + A1[7]*b.y + A1[8]*c.y;
        v[3].z = A1[6]*a.z + A1[7]*b.z + A1[8]*c.z;
        v[3].w = A1[6]*a.w + A1[7]*b.w + A1[8]*c.w;
    }
#pragma unroll
    for (int i = 0; i < 4; i++) m4[(4*tid + i) ^ p] = v[i];
    __syncthreads();
}

// single-qubit rotation on qubit q >= 2 (scalar, conflict-free under swizzle)
__device__ __forceinline__ void rot_q(float* m, const float* A, int q, int tid)
{
    const int d = 1 << (2*q), lm = d - 1;
#pragma unroll
    for (int f = 0; f < 4; f++) {
        int rest = tid + f*256;
        int s0 = ((rest >> (2*q)) << (2*q + 2)) | (rest & lm);
        int ix = SW(s0 + d), iy = SW(s0 + 2*d), iz = SW(s0 + 3*d);
        float vx = m[ix], vy = m[iy], vz = m[iz];
        m[ix] = A[0]*vx + A[1]*vy + A[2]*vz;
        m[iy] = A[3]*vx + A[4]*vy + A[5]*vz;
        m[iz] = A[6]*vx + A[7]*vy + A[8]*vz;
    }
    __syncthreads();
}

__device__ __forceinline__ void ring_pass(float* m, const short* tb, int tid, bool dep)
{
    float v[16]; int tg[16];
#pragma unroll
    for (int e = 0; e < 16; e++) {
        int s = tid + e*256;
        float x = m[SW(s)];
        if (dep) {
            float sc = 1.f;
#pragma unroll
            for (int q = 0; q < 6; q++)
                if ((s >> (2*q)) & 3) sc *= (q < 5) ? LAM12 : LAM1;
            x *= sc;
        }
        v[e] = x;
        tg[e] = tb[s];
    }
    __syncthreads();
#pragma unroll
    for (int e = 0; e < 16; e++)
        m[SW(tg[e] & 4095)] = (tg[e] & 4096) ? -v[e] : v[e];
    __syncthreads();
}

// ---------- kernel 1: PTM evolution (blocks 0..5) + coalesced tiled GEMM (6..133) ----------
__global__ void __launch_bounds__(256) k1(const float* __restrict__ x, const float* __restrict__ W1,
                                          const float* __restrict__ sw, const float* __restrict__ tw)
{
    __shared__ __align__(16) char su[SMEM_BYTES];
    const int tid = threadIdx.x;
    const int blk = blockIdx.x;

    if (blk < NPTM) {
        float* m = reinterpret_cast<float*>(su);
        short* rtab = reinterpret_cast<short*>(su + 16384);            // [3][4096]
        float (*mats)[10] = reinterpret_cast<float(*)[10]>(su + 40960); // [30][10]

        // bulk-copy ring tables to smem (issued first; latency hidden)
        {
            const uint4* srcT = reinterpret_cast<const uint4*>(&g_tabs.ring[0][0]);
            uint4* dstT = reinterpret_cast<uint4*>(rtab);
#pragma unroll
            for (int i = 0; i < 6; i++) dstT[tid + i*256] = srcT[tid + i*256];
        }
        // precompute all 30 adjoint rotation matrices in parallel
        if (tid < 30) {
            const float* wsrc = (tid < 18) ? (sw + tid*3) : (tw + (tid - 18)*3);
            float sp, cp, st, ct, sw_, cw_;
            sincosf(wsrc[0], &sp, &cp);
            sincosf(wsrc[1], &st, &ct);
            sincosf(wsrc[2], &sw_, &cw_);
            mats[tid][0] =  cp*ct*cw_ - sp*sw_;
            mats[tid][1] =  cp*ct*sw_ + sp*cw_;
            mats[tid][2] = -cp*st;
            mats[tid][3] = -sp*ct*cw_ - cp*sw_;
            mats[tid][4] = -sp*ct*sw_ + cp*cw_;
            mats[tid][5] =  sp*st;
            mats[tid][6] =  st*cw_;
            mats[tid][7] =  st*sw_;
            mats[tid][8] =  ct;
        }
        const int k = blk;    // observable Z_k
        const int z0 = 3 << (2*k);
#pragma unroll
        for (int e = 0; e < 16; e++) {
            int s = tid + e*256;
            m[SW(s)] = (s == z0) ? LAM1 : 0.f;     // final depolarize folded
        }
        __syncthreads();

        // adjoint: 5 x [ring; rot layer]; (ring r, dep, mat base):
        // (2,0,24) (1,0,18) (3,1,12) (2,0,6) (1,0,0)
        const int rsel[5] = {1, 0, 2, 1, 0};       // rtab index = r-1
        const int mb[5]   = {24, 18, 12, 6, 0};
#pragma unroll 1
        for (int L = 0; L < 5; L++) {
            ring_pass(m, rtab + rsel[L]*4096, tid, L == 2);
            rot01_pass(m, mats[mb[L] + 0], mats[mb[L] + 1], tid);
            rot_q(m, mats[mb[L] + 2], 2, tid);
            rot_q(m, mats[mb[L] + 3], 3, tid);
            rot_q(m, mats[mb[L] + 4], 4, tid);
            rot_q(m, mats[mb[L] + 5], 5, tid);
        }

        // compress to base-3 transposed table (Y components drop: initial Bloch y=0)
        for (int i = tid; i < 768; i += 256)
            g_Tct[i*8 + k] = (i < 729) ? m[SW((int)g_tabs.s4of[i])] : 0.f;
        if (tid < 192) {  // zero pad lanes 6,7 (one PTM block suffices, do in all - idempotent)
            int i = tid * 4 + (k & 3);  // spread; harmless duplicate zeroing
        }
    } else {
        const int g    = blk - NPTM;
        const int rowT = g >> 4;            // 0..7 : 32-row tiles
        const int colT = (g >> 2) & 3;      // 0..3 : 64-col tiles
        const int kp   = g & 3;             // 0..3 : 196-K slices
        const int row0 = rowT * 32, col0 = colT * 64;

        float* ws = reinterpret_cast<float*>(su);            // [64][101]
        float* xs = reinterpret_cast<float*>(su + 25856);    // [32][100]
        const int lane = tid & 31, wrp = tid >> 5;
        const int r0 = wrp * 4;

        float acc[4][2] = {{0.f,0.f},{0.f,0.f},{0.f,0.f},{0.f,0.f}};
        const float2* W1_2 = reinterpret_cast<const float2*>(W1);
        const float2* x_2  = reinterpret_cast<const float2*>(x);

#pragma unroll 1
        for (int ch = 0; ch < 2; ch++) {
            const int kof = kp*98 + ch*49;   // in float2 units
            for (int idx = tid; idx < 64*49; idx += 256) {
                int c = idx / 49, j2 = idx - c*49;
                float2 wv = W1_2[(col0 + c)*392 + kof + j2];
                ws[c*101 + 2*j2]     = wv.x;
                ws[c*101 + 2*j2 + 1] = wv.y;
            }
            if (tid < 128) ws[(tid >> 1)*101 + 98 + (tid & 1)] = 0.f;
            for (int idx = tid; idx < 32*49; idx += 256) {
                int r = idx / 49, j2 = idx - r*49;
                float2 xv = x_2[(row0 + r)*392 + kof + j2];
                xs[r*100 + 2*j2]     = xv.x;
                xs[r*100 + 2*j2 + 1] = xv.y;
            }
            if (tid < 64) xs[(tid >> 1)*100 + 98 + (tid & 1)] = 0.f;
            __syncthreads();

#pragma unroll 5
            for (int j = 0; j < 25; j++) {
                float4 x0 = *reinterpret_cast<float4*>(xs + (r0+0)*100 + 4*j);
                float4 x1 = *reinterpret_cast<float4*>(xs + (r0+1)*100 + 4*j);
                float4 x2 = *reinterpret_cast<float4*>(xs + (r0+2)*100 + 4*j);
                float4 x3 = *reinterpret_cast<float4*>(xs + (r0+3)*100 + 4*j);
                float w0[4], w1[4];
#pragma unroll
                for (int mm = 0; mm < 4; mm++) {
                    w0[mm] = ws[lane*101 + 4*j + mm];
                    w1[mm] = ws[(lane + 32)*101 + 4*j + mm];
                }
                acc[0][0] = fmaf(x0.x, w0[0], acc[0][0]); acc[0][0] = fmaf(x0.y, w0[1], acc[0][0]);
                acc[0][0] = fmaf(x0.z, w0[2], acc[0][0]); acc[0][0] = fmaf(x0.w, w0[3], acc[0][0]);
                acc[0][1] = fmaf(x0.x, w1[0], acc[0][1]); acc[0][1] = fmaf(x0.y, w1[1], acc[0][1]);
                acc[0][1] = fmaf(x0.z, w1[2], acc[0][1]); acc[0][1] = fmaf(x0.w, w1[3], acc[0][1]);
                acc[1][0] = fmaf(x1.x, w0[0], acc[1][0]); acc[1][0] = fmaf(x1.y, w0[1], acc[1][0]);
                acc[1][0] = fmaf(x1.z, w0[2], acc[1][0]); acc[1][0] = fmaf(x1.w, w0[3], acc[1][0]);
                acc[1][1] = fmaf(x1.x, w1[0], acc[1][1]); acc[1][1] = fmaf(x1.y, w1[1], acc[1][1]);
                acc[1][1] = fmaf(x1.z, w1[2], acc[1][1]); acc[1][1] = fmaf(x1.w, w1[3], acc[1][1]);
                acc[2][0] = fmaf(x2.x, w0[0], acc[2][0]); acc[2][0] = fmaf(x2.y, w0[1], acc[2][0]);
                acc[2][0] = fmaf(x2.z, w0[2], acc[2][0]); acc[2][0] = fmaf(x2.w, w0[3], acc[2][0]);
                acc[2][1] = fmaf(x2.x, w1[0], acc[2][1]); acc[2][1] = fmaf(x2.y, w1[1], acc[2][1]);
                acc[2][1] = fmaf(x2.z, w1[2], acc[2][1]); acc[2][1] = fmaf(x2.w, w1[3], acc[2][1]);
                acc[3][0] = fmaf(x3.x, w0[0], acc[3][0]); acc[3][0] = fmaf(x3.y, w0[1], acc[3][0]);
                acc[3][0] = fmaf(x3.z, w0[2], acc[3][0]); acc[3][0] = fmaf(x3.w, w0[3], acc[3][0]);
                acc[3][1] = fmaf(x3.x, w1[0], acc[3][1]); acc[3][1] = fmaf(x3.y, w1[1], acc[3][1]);
                acc[3][1] = fmaf(x3.z, w1[2], acc[3][1]); acc[3][1] = fmaf(x3.w, w1[3], acc[3][1]);
            }
            __syncthreads();
        }
#pragma unroll
        for (int i = 0; i < 4; i++) {
            int row = row0 + r0 + i;
            g_hp[kp*65536 + row*256 + col0 + lane]      = acc[i][0];
            g_hp[kp*65536 + row*256 + col0 + 32 + lane] = acc[i][1];
        }
    }
}

// ---------- kernel 2: 2 rows/block; bias/ReLU + LN + W2/tanh + quantum eval + projection ----------
__global__ void __launch_bounds__(256) k2(const float* __restrict__ b1v,
                                          const float* __restrict__ lng, const float* __restrict__ lnb,
                                          const float* __restrict__ W2, const float* __restrict__ b2,
                                          const float* __restrict__ Wp, const float* __restrict__ bp,
                                          float* __restrict__ out)
{
    __shared__ float hnA[HID], hnB[HID];
    __shared__ float4 red[8];
    __shared__ float tqA[18], tqB[18];
    __shared__ float ploA[27], phiA[27], ploB[27], phiB[27];
    __shared__ float r6A[8][6], r6B[8][6];
    __shared__ float evA[NQ], evB[NQ];

    const int tid = threadIdx.x;
    const int lane = tid & 31, w = tid >> 5;
    const int rA = blockIdx.x * 2, rB = rA + 1;

    // prefetch observable tables (vectorized: [term][8] layout)
    const float4* Tct4 = reinterpret_cast<const float4*>(g_Tct);
    float4 tA[3], tB[3];
#pragma unroll
    for (int j = 0; j < 3; j++) {
        int ss = tid + j * 256;           // < 768, zero-padded
        tA[j] = Tct4[ss*2];
        tB[j] = Tct4[ss*2 + 1];
    }
    float w2r[8];
    if (w < NQ) {
#pragma unroll
        for (int it = 0; it < 8; it++) w2r[it] = W2[w*256 + lane + it*32];
    }

    float hA = g_hp[rA*HID + tid] + g_hp[1*(BATCH*HID) + rA*HID + tid]
             + g_hp[2*(BATCH*HID) + rA*HID + tid] + g_hp[3*(BATCH*HID) + rA*HID + tid] + b1v[tid];
    float hB = g_hp[rB*HID + tid] + g_hp[1*(BATCH*HID) + rB*HID + tid]
             + g_hp[2*(BATCH*HID) + rB*HID + tid] + g_hp[3*(BATCH*HID) + rB*HID + tid] + b1v[tid];
    hA = fmaxf(hA, 0.f);
    hB = fmaxf(hB, 0.f);

    float s0 = hA, q0 = hA*hA, s1 = hB, q1 = hB*hB;
#pragma unroll
    for (int o = 16; o > 0; o >>= 1) {
        s0 += __shfl_down_sync(~0u, s0, o);
        q0 += __shfl_down_sync(~0u, q0, o);
        s1 += __shfl_down_sync(~0u, s1, o);
        q1 += __shfl_down_sync(~0u, q1, o);
    }
    if (lane == 0) red[w] = make_float4(s0, q0, s1, q1);
    __syncthreads();
    if (tid < 8) {
        float4 t = red[tid];
#pragma unroll
        for (int o = 4; o > 0; o >>= 1) {
            t.x += __shfl_down_sync(0xffu, t.x, o);
            t.y += __shfl_down_sync(0xffu, t.y, o);
            t.z += __shfl_down_sync(0xffu, t.z, o);
            t.w += __shfl_down_sync(0xffu, t.w, o);
        }
        if (tid == 0) red[0] = t;
    }
    __syncthreads();
    float4 R = red[0];
    float muA = R.x * (1.f/256.f), vaA = R.y * (1.f/256.f) - muA*muA;
    float muB = R.z * (1.f/256.f), vaB = R.w * (1.f/256.f) - muB*muB;
    float gg = lng[tid], bb = lnb[tid];
    hnA[tid] = (hA - muA) * rsqrtf(vaA + 1e-5f) * gg + bb;
    hnB[tid] = (hB - muB) * rsqrtf(vaB + 1e-5f) * gg + bb;
    __syncthreads();

    if (w < NQ) {
        float pA = 0.f, pB = 0.f;
#pragma unroll
        for (int it = 0; it < 8; it++) {
            int kk = lane + it * 32;
            pA = fmaf(hnA[kk], w2r[it], pA);
            pB = fmaf(hnB[kk], w2r[it], pB);
        }
#pragma unroll
        for (int o = 16; o > 0; o >>= 1) {
            pA += __shfl_down_sync(~0u, pA, o);
            pB += __shfl_down_sync(~0u, pB, o);
        }
        if (lane == 0) {
            float bw = b2[w];
            float zA = tanhf(pA + bw), zB = tanhf(pB + bw);
            float snA, cnA, snB, cnB;
            sincosf(PI_F * zA, &snA, &cnA);
            sincosf(PI_F * zB, &snB, &cnB);
            tqA[w*3] = 1.f; tqA[w*3+1] = LAM1 * snA; tqA[w*3+2] = LAM1 * cnA;
            tqB[w*3] = 1.f; tqB[w*3+1] = LAM1 * snB; tqB[w*3+2] = LAM1 * cnB;
        }
    }
    __syncthreads();

    if (tid < 27) {
        int d0 = tid % 3, d1 = (tid / 3) % 3, d2 = tid / 9;
        ploA[tid] = tqA[d0]     * tqA[3 + d1]  * tqA[6 + d2];
        phiA[tid] = tqA[9 + d0] * tqA[12 + d1] * tqA[15 + d2];
        ploB[tid] = tqB[d0]     * tqB[3 + d1]  * tqB[6 + d2];
        phiB[tid] = tqB[9 + d0] * tqB[12 + d1] * tqB[15 + d2];
    }
    __syncthreads();

    float accA[NQ] = {0,0,0,0,0,0}, accB[NQ] = {0,0,0,0,0,0};
#pragma unroll
    for (int j = 0; j < 3; j++) {
        int ss = tid + j * 256;
        int sc = (ss < 729) ? ss : 0;      // padded table rows are zero
        int lo = sc % 27, hi = sc / 27;
        float prA = ploA[lo] * phiA[hi];
        float prB = ploB[lo] * phiB[hi];
        accA[0] = fmaf(prA, tA[j].x, accA[0]); accB[0] = fmaf(prB, tA[j].x, accB[0]);
        accA[1] = fmaf(prA, tA[j].y, accA[1]); accB[1] = fmaf(prB, tA[j].y, accB[1]);
        accA[2] = fmaf(prA, tA[j].z, accA[2]); accB[2] = fmaf(prB, tA[j].z, accB[2]);
        accA[3] = fmaf(prA, tA[j].w, accA[3]); accB[3] = fmaf(prB, tA[j].w, accB[3]);
        accA[4] = fmaf(prA, tB[j].x, accA[4]); accB[4] = fmaf(prB, tB[j].x, accB[4]);
        accA[5] = fmaf(prA, tB[j].y, accA[5]); accB[5] = fmaf(prB, tB[j].y, accB[5]);
    }
#pragma unroll
    for (int k = 0; k < 6; k++) {
        float a = accA[k], b = accB[k];
#pragma unroll
        for (int o = 16; o > 0; o >>= 1) {
            a += __shfl_down_sync(~0u, a, o);
            b += __shfl_down_sync(~0u, b, o);
        }
        if (lane == 0) { r6A[w][k] = a; r6B[w][k] = b; }
    }
    __syncthreads();
    if (tid < NQ) {
        float t = 0.f;
#pragma unroll
        for (int ww = 0; ww < 8; ww++) t += r6A[ww][tid];
        evA[tid] = t;
    } else if (tid >= 32 && tid < 32 + NQ) {
        int k = tid - 32;
        float t = 0.f;
#pragma unroll
        for (int ww = 0; ww < 8; ww++) t += r6B[ww][k];
        evB[k] = t;
    }
    __syncthreads();
    if (tid < 2) {
        float o = bp[tid];
#pragma unroll
        for (int kq = 0; kq < NQ; kq++) o = fmaf(evA[kq], Wp[tid*NQ + kq], o);
        out[rA*2 + tid] = o;
    } else if (tid >= 32 && tid < 34) {
        int t2 = tid - 32;
        float o = bp[t2];
#pragma unroll
        for (int kq = 0; kq < NQ; kq++) o = fmaf(evB[kq], Wp[t2*NQ + kq], o);
        out[rB*2 + t2] = o;
    }
}

extern "C" void kernel_launch(void* const* d_in, const int* in_sizes, int n_in,
                              void* d_out, int out_size)
{
    const float* x        = (const float*)d_in[0];
    const float* W1       = (const float*)d_in[1];
    const float* b1       = (const float*)d_in[2];
    const float* ln_g     = (const float*)d_in[3];
    const float* ln_b     = (const float*)d_in[4];
    const float* W2       = (const float*)d_in[5];
    const float* b2       = (const float*)d_in[6];
    const float* shared_w = (const float*)d_in[7];
    const float* task_w   = (const float*)d_in[8];
    const float* Wp       = (const float*)d_in[9];
    const float* bp       = (const float*)d_in[10];
    float* out = (float*)d_out;

    k1<<<NPTM + GEMM_BLOCKS, 256>>>(x, W1, shared_w, task_w);
    k2<<<BATCH / 2, 256>>>(b1, ln_g, ln_b, W2, b2, Wp, bp, out);
}